// round 6
// baseline (speedup 1.0000x reference)
#include <cuda_runtime.h>
#include <cuda_bf16.h>
#include <math.h>
#include <stdint.h>

#define EMB 1024
#define HEADS 16
#define HDIM 64
#define MAX_TOK (4 * 2048)

// Scratch (allocation-free rule: __device__ globals)
__device__ float g_q[MAX_TOK * EMB];
__device__ float g_k[MAX_TOK * EMB];
__device__ float g_v[MAX_TOK * EMB];
__device__ float g_ao[MAX_TOK * EMB];

// ---- tf32 helpers ----
__device__ __forceinline__ uint32_t f2tf32(float x) {
    uint32_t r;
    asm("cvt.rna.tf32.f32 %0, %1;" : "=r"(r) : "f"(x));
    return r;
}
__device__ __forceinline__ void mma_tf32(float& c0, float& c1, float& c2, float& c3,
                                         uint32_t a0, uint32_t a1, uint32_t a2, uint32_t a3,
                                         uint32_t b0, uint32_t b1) {
    asm("mma.sync.aligned.m16n8k8.row.col.f32.tf32.tf32.f32 "
        "{%0,%1,%2,%3}, {%4,%5,%6,%7}, {%8,%9}, {%0,%1,%2,%3};"
        : "+f"(c0), "+f"(c1), "+f"(c2), "+f"(c3)
        : "r"(a0), "r"(a1), "r"(a2), "r"(a3), "r"(b0), "r"(b1));
}

// XOR-swizzled smem layout, 16 floats per row (no padding):
//   float index = row*16 + ((c ^ ((row>>1)&3)) << 2) + j   where kcol = 4c+j.
// Stores (STS.128): per 8-lane phase addr4%8 = 4*(q&1) + (c^((q>>1)&3))
//   -> all 8 slots distinct -> conflict-free.
// Fragment reads (LDS.32): bank = 16*(grp&1) + 4*(c0^(grp>>1)) + tg
//   -> 5 independent bits -> all 32 lanes distinct -> conflict-free
//   (holds for A rows r+grp, r+8+grp and B rows wn+nt*8+grp: all offsets
//    are even / =0 mod 4 where required).
__device__ __forceinline__ int sw_idx(int row, int kcol) {
    return row * 16 + ((((kcol >> 2) ^ ((row >> 1) & 3)) << 2) | (kcol & 3));
}

// ---------------------------------------------------------------------------
// tf32 tensor-core GEMM: C[M,N] = A[M,K] @ W[N,K]^T + bias[N]
// N = K = EMB = 1024. CTA tile 128x128, BK=16, 128 threads = 4 warps (2x2),
// warp tile 64x64 = 4x8 m16n8k8 MMA tiles.
// Double-buffered smem (2 stages), ONE __syncthreads per K-iteration.
// Inputs rounded to tf32 with cvt.rna (unbiased; rel err ~1e-4 at K=1024).
// ---------------------------------------------------------------------------
#define BK 16

__global__ __launch_bounds__(128) void gemm_tf32_tn_bias(
    const float* __restrict__ A,
    const float* __restrict__ W,
    const float* __restrict__ bias,
    float* __restrict__ C)
{
    const int K = EMB;
    const int N = EMB;
    __shared__ __align__(16) float As[2][128 * 16];
    __shared__ __align__(16) float Bs[2][128 * 16];

    const int tid  = threadIdx.x;
    const int bm   = blockIdx.y * 128;
    const int bn   = blockIdx.x * 128;
    const int warp = tid >> 5;
    const int lane = tid & 31;
    const int wm   = (warp >> 1) * 64;   // warp m-offset: 0 or 64
    const int wn   = (warp & 1) * 64;    // warp n-offset: 0 or 64
    const int grp  = lane >> 2;          // 0..7
    const int tg   = lane & 3;           // 0..3

    // gmem tile load mapping: 128 rows x 16 k-cols = 512 float4 per matrix,
    // 4 per thread. idx = i*128 + tid; row = idx>>2, c = idx&3 (float4 col)
    float4 areg[4], wreg[4];

    const float* Abase = A + (size_t)bm * K;
    const float* Wbase = W + (size_t)bn * K;

    auto gload = [&](int k0) {
#pragma unroll
        for (int i = 0; i < 4; i++) {
            int idx = i * 128 + tid;
            int row = idx >> 2;
            int kc  = (idx & 3) * 4;
            areg[i] = *(const float4*)(Abase + (size_t)row * K + k0 + kc);
            wreg[i] = *(const float4*)(Wbase + (size_t)row * K + k0 + kc);
        }
    };
    auto sstore = [&](int buf) {
        float* Ad = As[buf];
        float* Bd = Bs[buf];
#pragma unroll
        for (int i = 0; i < 4; i++) {
            int idx = i * 128 + tid;
            int row = idx >> 2;
            int c   = idx & 3;
            int cs  = (c ^ ((row >> 1) & 3)) << 2;   // swizzled float4 slot
            uint4 av, bv;
            av.x = f2tf32(areg[i].x); av.y = f2tf32(areg[i].y);
            av.z = f2tf32(areg[i].z); av.w = f2tf32(areg[i].w);
            bv.x = f2tf32(wreg[i].x); bv.y = f2tf32(wreg[i].y);
            bv.z = f2tf32(wreg[i].z); bv.w = f2tf32(wreg[i].w);
            *(uint4*)&Ad[row * 16 + cs] = av;
            *(uint4*)&Bd[row * 16 + cs] = bv;
        }
    };

    float acc[4][8][4];   // [mtile][ntile][c0..c3]
#pragma unroll
    for (int mt = 0; mt < 4; mt++)
#pragma unroll
        for (int nt = 0; nt < 8; nt++)
#pragma unroll
            for (int c = 0; c < 4; c++) acc[mt][nt][c] = 0.0f;

    // prologue: load + store tile 0, one barrier
    gload(0);
    sstore(0);
    __syncthreads();

    const int NIT = K / BK;   // 64
    for (int it = 0; it < NIT; it++) {
        const int s = it & 1;
        const bool has_next = (it + 1 < NIT);
        if (has_next) gload((it + 1) * BK);   // LDG latency hides under compute

        const float* Asb = As[s];
        const float* Bsb = Bs[s];
#pragma unroll
        for (int kk = 0; kk < BK / 8; kk++) {
            const int kb = kk * 8;
            // A fragments: 4 m-tiles (m16n8k8 row-major A layout)
            uint32_t af[4][4];
#pragma unroll
            for (int mt = 0; mt < 4; mt++) {
                const int r = wm + mt * 16;
                af[mt][0] = __float_as_uint(Asb[sw_idx(r + grp,     kb + tg)]);
                af[mt][1] = __float_as_uint(Asb[sw_idx(r + grp + 8, kb + tg)]);
                af[mt][2] = __float_as_uint(Asb[sw_idx(r + grp,     kb + tg + 4)]);
                af[mt][3] = __float_as_uint(Asb[sw_idx(r + grp + 8, kb + tg + 4)]);
            }
            // B fragments: 8 n-tiles; col-major B = Ws[n][k]
            uint32_t bf[8][2];
#pragma unroll
            for (int nt = 0; nt < 8; nt++) {
                const int n = wn + nt * 8 + grp;
                bf[nt][0] = __float_as_uint(Bsb[sw_idx(n, kb + tg)]);
                bf[nt][1] = __float_as_uint(Bsb[sw_idx(n, kb + tg + 4)]);
            }
#pragma unroll
            for (int mt = 0; mt < 4; mt++)
#pragma unroll
                for (int nt = 0; nt < 8; nt++)
                    mma_tf32(acc[mt][nt][0], acc[mt][nt][1], acc[mt][nt][2], acc[mt][nt][3],
                             af[mt][0], af[mt][1], af[mt][2], af[mt][3],
                             bf[nt][0], bf[nt][1]);
        }

        if (has_next) {
            sstore(s ^ 1);    // stage s^1 last read in iter it-1 (pre-barrier)
            __syncthreads();
        }
    }

    // epilogue: c0,c1 -> (row, col..col+1); c2,c3 -> (row+8, col..col+1)
#pragma unroll
    for (int mt = 0; mt < 4; mt++) {
#pragma unroll
        for (int nt = 0; nt < 8; nt++) {
            const int row = bm + wm + mt * 16 + grp;
            const int col = bn + wn + nt * 8 + tg * 2;
            float2 b2 = *(const float2*)(bias + col);
            float2 o0 = make_float2(acc[mt][nt][0] + b2.x, acc[mt][nt][1] + b2.y);
            float2 o1 = make_float2(acc[mt][nt][2] + b2.x, acc[mt][nt][3] + b2.y);
            *(float2*)(C + (size_t)row * N + col)       = o0;
            *(float2*)(C + (size_t)(row + 8) * N + col) = o1;
        }
    }
}

// ---------------------------------------------------------------------------
// Per-token head-head attention (fp32 SIMT; ~1% of FLOPs).
// One CTA (256 threads) per token. q,k,v rows viewed as [16 heads][64 dim].
// scores[h][g] = (q[h]·k[g]) / 8 ; softmax over g ; out[h] = attn[h] @ v
// ---------------------------------------------------------------------------
__global__ __launch_bounds__(256) void headattn_kernel(
    const float* __restrict__ q,
    const float* __restrict__ k,
    const float* __restrict__ v,
    float* __restrict__ out)
{
    __shared__ __align__(16) float qs[EMB];
    __shared__ __align__(16) float ks[EMB];
    __shared__ __align__(16) float vs[EMB];
    __shared__ float sc[HEADS * HEADS];

    const int tid = threadIdx.x;
    const size_t base = (size_t)blockIdx.x * EMB;

    {
        int idx = tid * 4;
        *(float4*)&qs[idx] = *(const float4*)(q + base + idx);
        *(float4*)&ks[idx] = *(const float4*)(k + base + idx);
        *(float4*)&vs[idx] = *(const float4*)(v + base + idx);
    }
    __syncthreads();

    {
        int h = tid >> 4, g = tid & 15;
        const float* qh = &qs[h * HDIM];
        const float* kg = &ks[g * HDIM];
        float s = 0.0f;
#pragma unroll
        for (int d = 0; d < HDIM; d += 4) {
            float4 qv = *(const float4*)(qh + d);
            float4 kv = *(const float4*)(kg + d);
            s = fmaf(qv.x, kv.x, s);
            s = fmaf(qv.y, kv.y, s);
            s = fmaf(qv.z, kv.z, s);
            s = fmaf(qv.w, kv.w, s);
        }
        sc[tid] = s * 0.125f;   // HEAD_DIM^-0.5 = 1/8
    }
    __syncthreads();

    if (tid < HEADS) {
        float* row = &sc[tid * HEADS];
        float m = row[0];
#pragma unroll
        for (int g = 1; g < HEADS; g++) m = fmaxf(m, row[g]);
        float sum = 0.0f;
        float e[HEADS];
#pragma unroll
        for (int g = 0; g < HEADS; g++) { e[g] = __expf(row[g] - m); sum += e[g]; }
        float inv = 1.0f / sum;
#pragma unroll
        for (int g = 0; g < HEADS; g++) row[g] = e[g] * inv;
    }
    __syncthreads();

    {
        int h = tid >> 4;
        int d = (tid & 15) * 4;
        const float* attn = &sc[h * HEADS];
        float4 accv = make_float4(0.f, 0.f, 0.f, 0.f);
#pragma unroll
        for (int g = 0; g < HEADS; g++) {
            float w = attn[g];
            float4 vv = *(const float4*)&vs[g * HDIM + d];
            accv.x = fmaf(w, vv.x, accv.x);
            accv.y = fmaf(w, vv.y, accv.y);
            accv.z = fmaf(w, vv.z, accv.z);
            accv.w = fmaf(w, vv.w, accv.w);
        }
        *(float4*)(out + base + tid * 4) = accv;
    }
}

// ---------------------------------------------------------------------------
// launch
// ---------------------------------------------------------------------------
extern "C" void kernel_launch(void* const* d_in, const int* in_sizes, int n_in,
                              void* d_out, int out_size)
{
    const float* values = (const float*)d_in[0];
    const float* keys   = (const float*)d_in[1];
    const float* query  = (const float*)d_in[2];
    const float* Wv     = (const float*)d_in[3];
    const float* bv     = (const float*)d_in[4];
    const float* Wk     = (const float*)d_in[5];
    const float* bk     = (const float*)d_in[6];
    const float* Wq     = (const float*)d_in[7];
    const float* bq     = (const float*)d_in[8];
    const float* Wo     = (const float*)d_in[9];
    const float* bo     = (const float*)d_in[10];

    const int M = in_sizes[0] / EMB;   // tokens = B*S (8192)

    float* q = nullptr; float* k = nullptr; float* v = nullptr; float* ao = nullptr;
    cudaGetSymbolAddress((void**)&q,  g_q);
    cudaGetSymbolAddress((void**)&k,  g_k);
    cudaGetSymbolAddress((void**)&v,  g_v);
    cudaGetSymbolAddress((void**)&ao, g_ao);

    dim3 ggrid(EMB / 128, M / 128);
    dim3 gblk(128);

    // projections (tf32 tensor cores)
    gemm_tf32_tn_bias<<<ggrid, gblk>>>(values, Wv, bv, v);
    gemm_tf32_tn_bias<<<ggrid, gblk>>>(keys,   Wk, bk, k);
    gemm_tf32_tn_bias<<<ggrid, gblk>>>(query,  Wq, bq, q);

    // per-token head-head attention (fp32)
    headattn_kernel<<<M, 256>>>(q, k, v, ao);

    // output projection -> d_out
    gemm_tf32_tn_bias<<<ggrid, gblk>>>(ao, Wo, bo, (float*)d_out);
}

// round 10
// speedup vs baseline: 1.1403x; 1.1403x over previous
#include <cuda_runtime.h>
#include <cuda_bf16.h>
#include <math.h>
#include <stdint.h>

#define EMB 1024
#define HEADS 16
#define HDIM 64
#define MAX_TOK (4 * 2048)

// Scratch (allocation-free rule: __device__ globals)
__device__ float g_q[MAX_TOK * EMB];
__device__ float g_k[MAX_TOK * EMB];
__device__ float g_v[MAX_TOK * EMB];
__device__ float g_ao[MAX_TOK * EMB];

// ---- tf32 helpers ----
__device__ __forceinline__ uint32_t f2tf32(float x) {
    uint32_t r;
    asm("cvt.rna.tf32.f32 %0, %1;" : "=r"(r) : "f"(x));
    return r;
}
__device__ __forceinline__ void mma_tf32(float& c0, float& c1, float& c2, float& c3,
                                         uint32_t a0, uint32_t a1, uint32_t a2, uint32_t a3,
                                         uint32_t b0, uint32_t b1) {
    asm("mma.sync.aligned.m16n8k8.row.col.f32.tf32.tf32.f32 "
        "{%0,%1,%2,%3}, {%4,%5,%6,%7}, {%8,%9}, {%0,%1,%2,%3};"
        : "+f"(c0), "+f"(c1), "+f"(c2), "+f"(c3)
        : "r"(a0), "r"(a1), "r"(a2), "r"(a3), "r"(b0), "r"(b1));
}

// XOR-swizzled smem layout, 16 floats per row (no padding):
//   float index = row*16 + ((c ^ ((row>>1)&3)) << 2) + j   where kcol = 4c+j.
// Stores (STS.128) and fragment reads (LDS.32) both conflict-free (verified
// lane-by-lane; see round-5 derivation).
__device__ __forceinline__ int sw_idx(int row, int kcol) {
    return row * 16 + ((((kcol >> 2) ^ ((row >> 1) & 3)) << 2) | (kcol & 3));
}

// ---------------------------------------------------------------------------
// tf32 tensor-core GEMM body: C[M,N] = A[M,K] @ W[N,K]^T + bias[N]
// N = K = EMB = 1024. CTA tile 256x128, BK=16, 256 threads = 8 warps (4x2),
// warp tile 64x64 = 4x8 m16n8k8 MMA tiles.
// ~200 regs/thread -> 1 CTA/SM (8 warps/SM), 48KB smem.
// Double-buffered smem, ONE __syncthreads per K-iteration.
// ---------------------------------------------------------------------------
#define BK 16

__device__ __forceinline__ void gemm_body(
    const float* __restrict__ A,
    const float* __restrict__ W,
    const float* __restrict__ bias,
    float* __restrict__ C,
    float (*As)[256 * 16], float (*Bs)[128 * 16])
{
    const int K = EMB;
    const int N = EMB;

    const int tid  = threadIdx.x;
    const int bm   = blockIdx.y * 256;
    const int bn   = blockIdx.x * 128;
    const int warp = tid >> 5;
    const int lane = tid & 31;
    const int wm   = (warp >> 1) * 64;   // warp m-offset: 0,64,128,192
    const int wn   = (warp & 1) * 64;    // warp n-offset: 0 or 64
    const int grp  = lane >> 2;          // 0..7
    const int tg   = lane & 3;           // 0..3

    // gmem tile staging: A 256x16 = 1024 float4 (4/thread), W 128x16 = 512 (2/thread)
    float4 areg[4], wreg[2];

    const float* Abase = A + (size_t)bm * K;
    const float* Wbase = W + (size_t)bn * K;

    auto gload = [&](int k0) {
#pragma unroll
        for (int i = 0; i < 4; i++) {
            int idx = i * 256 + tid;
            int row = idx >> 2;
            int kc  = (idx & 3) * 4;
            areg[i] = *(const float4*)(Abase + (size_t)row * K + k0 + kc);
        }
#pragma unroll
        for (int i = 0; i < 2; i++) {
            int idx = i * 256 + tid;
            int row = idx >> 2;
            int kc  = (idx & 3) * 4;
            wreg[i] = *(const float4*)(Wbase + (size_t)row * K + k0 + kc);
        }
    };
    auto sstore = [&](int buf) {
        float* Ad = As[buf];
        float* Bd = Bs[buf];
#pragma unroll
        for (int i = 0; i < 4; i++) {
            int idx = i * 256 + tid;
            int row = idx >> 2;
            int c   = idx & 3;
            int cs  = (c ^ ((row >> 1) & 3)) << 2;   // swizzled float4 slot
            uint4 av;
            av.x = f2tf32(areg[i].x); av.y = f2tf32(areg[i].y);
            av.z = f2tf32(areg[i].z); av.w = f2tf32(areg[i].w);
            *(uint4*)&Ad[row * 16 + cs] = av;
        }
#pragma unroll
        for (int i = 0; i < 2; i++) {
            int idx = i * 256 + tid;
            int row = idx >> 2;
            int c   = idx & 3;
            int cs  = (c ^ ((row >> 1) & 3)) << 2;
            uint4 bv;
            bv.x = f2tf32(wreg[i].x); bv.y = f2tf32(wreg[i].y);
            bv.z = f2tf32(wreg[i].z); bv.w = f2tf32(wreg[i].w);
            *(uint4*)&Bd[row * 16 + cs] = bv;
        }
    };

    float acc[4][8][4];   // [mtile][ntile][c0..c3]
#pragma unroll
    for (int mt = 0; mt < 4; mt++)
#pragma unroll
        for (int nt = 0; nt < 8; nt++)
#pragma unroll
            for (int c = 0; c < 4; c++) acc[mt][nt][c] = 0.0f;

    // prologue: load + store tile 0, one barrier
    gload(0);
    sstore(0);
    __syncthreads();

    const int NIT = K / BK;   // 64
    for (int it = 0; it < NIT; it++) {
        const int s = it & 1;
        const bool has_next = (it + 1 < NIT);
        if (has_next) gload((it + 1) * BK);   // LDG latency hides under compute

        const float* Asb = As[s];
        const float* Bsb = Bs[s];
#pragma unroll
        for (int kk = 0; kk < BK / 8; kk++) {
            const int kb = kk * 8;
            // A fragments: 4 m-tiles (m16n8k8 row-major A layout)
            uint32_t af[4][4];
#pragma unroll
            for (int mt = 0; mt < 4; mt++) {
                const int r = wm + mt * 16;
                af[mt][0] = __float_as_uint(Asb[sw_idx(r + grp,     kb + tg)]);
                af[mt][1] = __float_as_uint(Asb[sw_idx(r + grp + 8, kb + tg)]);
                af[mt][2] = __float_as_uint(Asb[sw_idx(r + grp,     kb + tg + 4)]);
                af[mt][3] = __float_as_uint(Asb[sw_idx(r + grp + 8, kb + tg + 4)]);
            }
            // B fragments: 8 n-tiles; col-major B = Ws[n][k]
            uint32_t bf[8][2];
#pragma unroll
            for (int nt = 0; nt < 8; nt++) {
                const int n = wn + nt * 8 + grp;
                bf[nt][0] = __float_as_uint(Bsb[sw_idx(n, kb + tg)]);
                bf[nt][1] = __float_as_uint(Bsb[sw_idx(n, kb + tg + 4)]);
            }
#pragma unroll
            for (int mt = 0; mt < 4; mt++)
#pragma unroll
                for (int nt = 0; nt < 8; nt++)
                    mma_tf32(acc[mt][nt][0], acc[mt][nt][1], acc[mt][nt][2], acc[mt][nt][3],
                             af[mt][0], af[mt][1], af[mt][2], af[mt][3],
                             bf[nt][0], bf[nt][1]);
        }

        if (has_next) {
            sstore(s ^ 1);    // stage s^1 last read in iter it-1 (pre-barrier)
            __syncthreads();
        }
    }

    // epilogue: c0,c1 -> (row, col..col+1); c2,c3 -> (row+8, col..col+1)
#pragma unroll
    for (int mt = 0; mt < 4; mt++) {
#pragma unroll
        for (int nt = 0; nt < 8; nt++) {
            const int row = bm + wm + mt * 16 + grp;
            const int col = bn + wn + nt * 8 + tg * 2;
            float2 b2 = *(const float2*)(bias + col);
            float2 o0 = make_float2(acc[mt][nt][0] + b2.x, acc[mt][nt][1] + b2.y);
            float2 o1 = make_float2(acc[mt][nt][2] + b2.x, acc[mt][nt][3] + b2.y);
            *(float2*)(C + (size_t)row * N + col)       = o0;
            *(float2*)(C + (size_t)(row + 8) * N + col) = o1;
        }
    }
}

// Fused Q/K/V projections: gridDim.z = 3 selects the (A, W, bias, C) set.
// Packs 768 CTAs into one launch instead of 3 launches of 256 CTAs
// (removes two launch/drain boundaries and two ragged wave tails).
__global__ __launch_bounds__(256) void gemm3_tf32_tn_bias(
    const float* A0, const float* W0, const float* b0, float* C0,
    const float* A1, const float* W1, const float* b1, float* C1,
    const float* A2, const float* W2, const float* b2, float* C2)
{
    __shared__ __align__(16) float As[2][256 * 16];
    __shared__ __align__(16) float Bs[2][128 * 16];
    const int z = blockIdx.z;
    const float* A = (z == 0) ? A0 : (z == 1) ? A1 : A2;
    const float* W = (z == 0) ? W0 : (z == 1) ? W1 : W2;
    const float* b = (z == 0) ? b0 : (z == 1) ? b1 : b2;
    float*       C = (z == 0) ? C0 : (z == 1) ? C1 : C2;
    gemm_body(A, W, b, C, As, Bs);
}

// Single GEMM (output projection)
__global__ __launch_bounds__(256) void gemm_tf32_tn_bias(
    const float* __restrict__ A,
    const float* __restrict__ W,
    const float* __restrict__ bias,
    float* __restrict__ C)
{
    __shared__ __align__(16) float As[2][256 * 16];
    __shared__ __align__(16) float Bs[2][128 * 16];
    gemm_body(A, W, bias, C, As, Bs);
}

// ---------------------------------------------------------------------------
// Per-token head-head attention.
// One CTA (256 threads) per token. q,k,v rows viewed as [16 heads][64 dim],
// staged in smem with row stride 68 (= HDIM+4) so the score-phase k reads
// ks[g*68+d] hit bank (4g+d)%32: the 16 active rows spread across banks with
// only the g/g+8 pair sharing -> 2 cyc/wavefront = the 256B crossbar floor
// (was 16-way conflicted at stride 64: bank = d%32 for ALL g -> measured
// L1=94.4%, 148.8us).
// ---------------------------------------------------------------------------
#define ATS 68   // attention smem row stride (floats)

__global__ __launch_bounds__(256) void headattn_kernel(
    const float* __restrict__ q,
    const float* __restrict__ k,
    const float* __restrict__ v,
    float* __restrict__ out)
{
    __shared__ __align__(16) float qs[HEADS * ATS];
    __shared__ __align__(16) float ks[HEADS * ATS];
    __shared__ __align__(16) float vs[HEADS * ATS];
    __shared__ float sc[HEADS * HEADS];

    const int tid = threadIdx.x;
    const size_t base = (size_t)blockIdx.x * EMB;
    const int sh = tid >> 4;          // head row 0..15
    const int sd = (tid & 15) * 4;    // dim offset 0..60

    // stage q,k,v: thread tid handles head sh, dims sd..sd+3
    {
        size_t g = base + sh * HDIM + sd;
        int    s = sh * ATS + sd;
        *(float4*)&qs[s] = *(const float4*)(q + g);
        *(float4*)&ks[s] = *(const float4*)(k + g);
        *(float4*)&vs[s] = *(const float4*)(v + g);
    }
    __syncthreads();

    // scores: thread (h,g) = (tid>>4, tid&15)
    {
        int h = tid >> 4, g = tid & 15;
        const float* qh = &qs[h * ATS];
        const float* kg = &ks[g * ATS];
        float s = 0.0f;
#pragma unroll
        for (int d = 0; d < HDIM; d += 4) {
            float4 qv = *(const float4*)(qh + d);
            float4 kv = *(const float4*)(kg + d);
            s = fmaf(qv.x, kv.x, s);
            s = fmaf(qv.y, kv.y, s);
            s = fmaf(qv.z, kv.z, s);
            s = fmaf(qv.w, kv.w, s);
        }
        sc[tid] = s * 0.125f;   // HEAD_DIM^-0.5 = 1/8
    }
    __syncthreads();

    // softmax over g, one thread per head
    if (tid < HEADS) {
        float* row = &sc[tid * HEADS];
        float m = row[0];
#pragma unroll
        for (int g = 1; g < HEADS; g++) m = fmaxf(m, row[g]);
        float sum = 0.0f;
        float e[HEADS];
#pragma unroll
        for (int g = 0; g < HEADS; g++) { e[g] = __expf(row[g] - m); sum += e[g]; }
        float inv = 1.0f / sum;
#pragma unroll
        for (int g = 0; g < HEADS; g++) row[g] = e[g] * inv;
    }
    __syncthreads();

    // out[h][d..d+3]: thread handles head sh, dims sd..sd+3
    {
        const float* attn = &sc[sh * HEADS];
        float4 accv = make_float4(0.f, 0.f, 0.f, 0.f);
#pragma unroll
        for (int g = 0; g < HEADS; g++) {
            float w = attn[g];
            float4 vv = *(const float4*)&vs[g * ATS + sd];
            accv.x = fmaf(w, vv.x, accv.x);
            accv.y = fmaf(w, vv.y, accv.y);
            accv.z = fmaf(w, vv.z, accv.z);
            accv.w = fmaf(w, vv.w, accv.w);
        }
        *(float4*)(out + base + sh * HDIM + sd) = accv;
    }
}

// ---------------------------------------------------------------------------
// launch
// ---------------------------------------------------------------------------
extern "C" void kernel_launch(void* const* d_in, const int* in_sizes, int n_in,
                              void* d_out, int out_size)
{
    const float* values = (const float*)d_in[0];
    const float* keys   = (const float*)d_in[1];
    const float* query  = (const float*)d_in[2];
    const float* Wv     = (const float*)d_in[3];
    const float* bv     = (const float*)d_in[4];
    const float* Wk     = (const float*)d_in[5];
    const float* bk     = (const float*)d_in[6];
    const float* Wq     = (const float*)d_in[7];
    const float* bq     = (const float*)d_in[8];
    const float* Wo     = (const float*)d_in[9];
    const float* bo     = (const float*)d_in[10];

    const int M = in_sizes[0] / EMB;   // tokens = B*S (8192)

    float* q = nullptr; float* k = nullptr; float* v = nullptr; float* ao = nullptr;
    cudaGetSymbolAddress((void**)&q,  g_q);
    cudaGetSymbolAddress((void**)&k,  g_k);
    cudaGetSymbolAddress((void**)&v,  g_v);
    cudaGetSymbolAddress((void**)&ao, g_ao);

    dim3 ggrid3(EMB / 128, M / 256, 3);
    dim3 ggrid(EMB / 128, M / 256);
    dim3 gblk(256);

    // fused Q/K/V projections (tf32 tensor cores), one launch
    gemm3_tf32_tn_bias<<<ggrid3, gblk>>>(
        values, Wv, bv, v,
        keys,   Wk, bk, k,
        query,  Wq, bq, q);

    // per-token head-head attention (fp32)
    headattn_kernel<<<M, 256>>>(q, k, v, ao);

    // output projection -> d_out
    gemm_tf32_tn_bias<<<ggrid, gblk>>>(ao, Wo, bo, (float*)d_out);
}